// round 3
// baseline (speedup 1.0000x reference)
#include <cuda_runtime.h>

// MinimalRNN scan, chunked-decoupled version.
//   h_{s+1} = exp(lc[s]) * h_s + exp(lv[s+1]),  h_0 = exp(lv[0]),  out[s] = h_{s+1}
// (B,T,H) row-major. T split into C chunks of L steps; each warp owns 32
// consecutive channels (one "strip") for one chunk. Carries flow between
// chunks via __device__ globals + release/acquire flags (chained scan).
// Chunk-major block ordering guarantees producers launch before consumers.
// Consumers reset their flag to 0 after reading -> graph-replay safe.

#define BB 16
#define TT 4096
#define HH 1024
#define CC 8
#define LL (TT / CC)          // 512
#define UU 8
#define NCH (BB * HH)         // 16384 channels
#define NSTRIP (NCH / 32)     // 512 strips

__device__ float g_carry[CC - 1][NCH];
__device__ int   g_flag[CC - 1][NSTRIP];   // zero-initialized (.bss)

__global__ void __launch_bounds__(128, 7)
minrnn_chunk_kernel(const float* __restrict__ lc,   // (B, T, H)
                    const float* __restrict__ lv,   // (B, T+1, H)
                    float* __restrict__ out)        // (B, T, H)
{
    const int chunk = blockIdx.x >> 7;            // chunk-major: chunk 0 first
    const int blk   = blockIdx.x & 127;
    const int ch    = blk * 128 + threadIdx.x;    // channel 0..16383
    const int strip = ch >> 5;
    const int lane  = threadIdx.x & 31;
    const int b     = ch >> 10;
    const int h     = ch & (HH - 1);

    const int s0 = chunk * LL;                    // first global step of chunk

    // Bases advanced to chunk start; per-step stride HH.
    const float* lcp  = lc + b * (TT * HH) + s0 * HH + h;           // lc[s0+i]
    const float* lvp2 = lv + b * ((TT + 1) * HH) + (s0 + 1) * HH + h; // lv[s0+i+1]
    float*       op   = out + b * (TT * HH) + s0 * HH + h;          // out[s0+i]

    float ca[UU], va[UU], cb[UU], vb[UU];

    // Issue two prefetch groups BEFORE waiting on the carry, so this chunk's
    // memory traffic overlaps the upstream chunks' compute.
#pragma unroll
    for (int i = 0; i < UU; i++) {
        ca[i] = lcp[i * HH];
        va[i] = lvp2[i * HH];
    }
#pragma unroll
    for (int i = 0; i < UU; i++) {
        cb[i] = lcp[(UU + i) * HH];
        vb[i] = lvp2[(UU + i) * HH];
    }

    // Acquire the incoming state h_{s0}.
    float hval;
    if (chunk == 0) {
        hval = __expf(lv[b * ((TT + 1) * HH) + h]);   // exp(lv[b,0,h])
    } else {
        int* flg = &g_flag[chunk - 1][strip];
        if (lane == 0) {
            while (atomicAdd(flg, 0) == 0) { __nanosleep(128); }
        }
        __syncwarp();
        __threadfence();                               // acquire
        hval = __ldcg(&g_carry[chunk - 1][ch]);
        if (lane == 0) *flg = 0;                       // reset for next replay
    }

    // Ping-pong mainloop over the chunk (L/(2U) = 32 iterations, no tail).
    for (int t0 = 0; t0 < LL; t0 += 2 * UU) {
#pragma unroll
        for (int i = 0; i < UU; i++) {
            hval = __expf(ca[i]) * hval + __expf(va[i]);
            op[(t0 + i) * HH] = hval;
        }
        if (t0 + 2 * UU < LL) {
#pragma unroll
            for (int i = 0; i < UU; i++) {
                ca[i] = lcp[(t0 + 2 * UU + i) * HH];
                va[i] = lvp2[(t0 + 2 * UU + i) * HH];
            }
        }
#pragma unroll
        for (int i = 0; i < UU; i++) {
            hval = __expf(cb[i]) * hval + __expf(vb[i]);
            op[(t0 + UU + i) * HH] = hval;
        }
        if (t0 + 3 * UU < LL) {
#pragma unroll
            for (int i = 0; i < UU; i++) {
                cb[i] = lcp[(t0 + 3 * UU + i) * HH];
                vb[i] = lvp2[(t0 + 3 * UU + i) * HH];
            }
        }
    }

    // Publish the outgoing carry h_{s0+L} (release).
    if (chunk < CC - 1) {
        __stcg(&g_carry[chunk][ch], hval);
        __threadfence();
        __syncwarp();
        if (lane == 0) atomicExch(&g_flag[chunk][strip], 1);
    }
}

extern "C" void kernel_launch(void* const* d_in, const int* in_sizes, int n_in,
                              void* d_out, int out_size)
{
    const float* log_coeffs = (const float*)d_in[0];   // (B, T, H)
    const float* log_values = (const float*)d_in[1];   // (B, T+1, H)
    float*       out        = (float*)d_out;           // (B, T, H)

    const int blocks = CC * (NCH / 128);   // 8 * 128 = 1024, chunk-major
    minrnn_chunk_kernel<<<blocks, 128>>>(log_coeffs, log_values, out);
}

// round 4
// speedup vs baseline: 1.5946x; 1.5946x over previous
#include <cuda_runtime.h>

// MinimalRNN scan via chunked A/B decomposition (chained carries).
//   h_{t} = exp(lc[t-1]) * h_{t-1} + exp(lv[t]),  h_0 = exp(lv[0])
// Over a chunk of L steps:  h_{s0+i} = A_i * h_{s0} + B_i   where
//   A_i = prod_{j<=i} exp(lc[s0+j]),  B_i = local scan with zero init.
// A_i and B_i are carry-independent -> ALL loads + local compute proceed
// without waiting. Only the 64 fixup-stores wait on the upstream carry.
// Carries flow through __device__ globals with release/acquire flags;
// consumers reset flags after reading (graph-replay safe).

#define BB 16
#define TT 4096
#define HH 1024
#define CC 64
#define LL (TT / CC)          // 64 steps per chunk
#define NCH (BB * HH)         // 16384 channels
#define NCOL (NCH / 128)      // 128 block-columns
#define NSTRIP (NCH / 32)     // 512 warp strips

__device__ float g_carry[(CC - 1) * NCH];
__device__ int   g_flag[(CC - 1) * NSTRIP];   // zero-init (.bss)

__global__ void __launch_bounds__(128)
minrnn_ab_kernel(const float* __restrict__ lc,   // (B, T, H)
                 const float* __restrict__ lv,   // (B, T+1, H)
                 float* __restrict__ out)        // (B, T, H)
{
    const int chunk = blockIdx.x >> 7;            // chunk-major ordering
    const int col   = blockIdx.x & 127;
    const int ch    = col * 128 + threadIdx.x;    // channel 0..16383
    const int strip = ch >> 5;
    const int lane  = threadIdx.x & 31;
    const int b     = ch >> 10;
    const int h     = ch & (HH - 1);
    const int s0    = chunk * LL;

    const float* lcp  = lc + b * (TT * HH) + s0 * HH + h;             // lc[s0+i]
    const float* lvp2 = lv + b * ((TT + 1) * HH) + (s0 + 1) * HH + h; // lv[s0+i+1]
    float*       op   = out + b * (TT * HH) + s0 * HH + h;            // out step s0+i

    // ---- Phase 1: load the whole chunk (128 independent LDGs, max MLP) ----
    float cc[LL], vv[LL];
#pragma unroll
    for (int i = 0; i < LL; i++) cc[i] = __ldcs(lcp + i * HH);
#pragma unroll
    for (int i = 0; i < LL; i++) vv[i] = __ldcs(lvp2 + i * HH);

    // ---- Phase 2: carry-independent local scan.  cc[i] <- A_i, vv[i] <- B_i
    float A = 1.0f, Bv = 0.0f;
#pragma unroll
    for (int i = 0; i < LL; i++) {
        const float e = __expf(cc[i]);
        A *= e;
        Bv = fmaf(e, Bv, __expf(vv[i]));
        cc[i] = A;
        vv[i] = Bv;
    }

    // ---- Phase 3: acquire incoming state h_{s0} ----
    float h0;
    if (chunk == 0) {
        h0 = __expf(__ldg(lv + b * ((TT + 1) * HH) + h));   // exp(lv[b,0,h])
    } else {
        int* flg = &g_flag[(chunk - 1) * NSTRIP + strip];
        if (lane == 0) {
            while (atomicAdd(flg, 0) == 0) { __nanosleep(64); }
        }
        __syncwarp();
        __threadfence();                                     // acquire
        h0 = __ldcg(&g_carry[(chunk - 1) * NCH + ch]);
        if (lane == 0) *flg = 0;                             // reset for replay
    }

    // ---- Phase 4: fixup + store (all independent) ----
#pragma unroll
    for (int i = 0; i < LL; i++) {
        __stcs(op + i * HH, fmaf(cc[i], h0, vv[i]));
    }

    // ---- Phase 5: publish outgoing carry (release) ----
    if (chunk < CC - 1) {
        __stcg(&g_carry[chunk * NCH + ch], fmaf(cc[LL - 1], h0, vv[LL - 1]));
        __threadfence();
        __syncwarp();
        if (lane == 0) atomicExch(&g_flag[chunk * NSTRIP + strip], 1);
    }
}

extern "C" void kernel_launch(void* const* d_in, const int* in_sizes, int n_in,
                              void* d_out, int out_size)
{
    const float* log_coeffs = (const float*)d_in[0];   // (B, T, H)
    const float* log_values = (const float*)d_in[1];   // (B, T+1, H)
    float*       out        = (float*)d_out;           // (B, T, H)

    const int blocks = CC * NCOL;      // 64 * 128 = 8192, chunk-major
    minrnn_ab_kernel<<<blocks, 128>>>(log_coeffs, log_values, out);
}

// round 5
// speedup vs baseline: 1.9457x; 1.2202x over previous
#include <cuda_runtime.h>

// MinimalRNN scan via chunked A/B decomposition with a fast carry chain.
//   h_t = exp(lc[t-1]) * h_{t-1} + exp(lv[t]),  h_0 = exp(lv[0])
// Chunk-local:  h_{s0+i} = A_i * h_{s0} + B_i   (A_i, B_i carry-independent)
// All loads + local scan proceed without waiting; only fixup stores wait.
// CRITICAL-PATH RULE: the outgoing carry  h_end = A_{L-1}*h0 + B_{L-1}
// is published IMMEDIATELY after h0 arrives, before any fixup stores,
// so a chain hop is just poll -> fma -> store -> fence -> flag.
// Flags are reset by their single consumer -> graph-replay safe.

#define BB 16
#define TT 4096
#define HH 1024
#define CC 64
#define LL (TT / CC)          // 64 steps per chunk
#define NCH (BB * HH)         // 16384 channels
#define NCOL (NCH / 128)      // 128 block-columns
#define NSTRIP (NCH / 32)     // 512 warp strips

__device__ float g_carry[(CC - 1) * NCH];
__device__ int   g_flag[(CC - 1) * NSTRIP];   // zero-init (.bss)

__global__ void __launch_bounds__(128)
minrnn_ab_kernel(const float* __restrict__ lc,   // (B, T, H)
                 const float* __restrict__ lv,   // (B, T+1, H)
                 float* __restrict__ out)        // (B, T, H)
{
    const int chunk = blockIdx.x >> 7;            // chunk-major ordering
    const int col   = blockIdx.x & 127;
    const int ch    = col * 128 + threadIdx.x;    // channel 0..16383
    const int strip = ch >> 5;
    const int lane  = threadIdx.x & 31;
    const int b     = ch >> 10;
    const int h     = ch & (HH - 1);
    const int s0    = chunk * LL;

    const float* lcp  = lc + b * (TT * HH) + s0 * HH + h;             // lc[s0+i]
    const float* lvp2 = lv + b * ((TT + 1) * HH) + (s0 + 1) * HH + h; // lv[s0+i+1]
    float*       op   = out + b * (TT * HH) + s0 * HH + h;            // out step s0+i

    // ---- Phase 1: load the whole chunk (128 independent LDGs, max MLP) ----
    float cc[LL], vv[LL];
#pragma unroll
    for (int i = 0; i < LL; i++) {
        cc[i] = __ldcs(lcp + i * HH);
        vv[i] = __ldcs(lvp2 + i * HH);
    }

    // ---- Phase 2: carry-independent local scan.  cc[i] <- A_i, vv[i] <- B_i
    float A = 1.0f, Bv = 0.0f;
#pragma unroll
    for (int i = 0; i < LL; i++) {
        const float e = __expf(cc[i]);
        A *= e;
        Bv = fmaf(e, Bv, __expf(vv[i]));
        cc[i] = A;
        vv[i] = Bv;
    }

    // ---- Phase 3: acquire incoming state h_{s0} ----
    float h0;
    if (chunk == 0) {
        h0 = __expf(__ldg(lv + b * ((TT + 1) * HH) + h));   // exp(lv[b,0,h])
    } else {
        int* flg = &g_flag[(chunk - 1) * NSTRIP + strip];
        if (lane == 0) {
            while (atomicAdd(flg, 0) == 0) { __nanosleep(32); }
        }
        __syncwarp();
        __threadfence();                                     // acquire
        h0 = __ldcg(&g_carry[(chunk - 1) * NCH + ch]);
        if (lane == 0) *flg = 0;                             // reset for replay
    }

    // ---- Phase 4: publish outgoing carry FIRST (shortest possible hop) ----
    if (chunk < CC - 1) {
        __stcg(&g_carry[chunk * NCH + ch], fmaf(A, h0, Bv)); // A,Bv = last A/B
        __threadfence();                                     // release
        __syncwarp();
        if (lane == 0) atomicExch(&g_flag[chunk * NSTRIP + strip], 1);
    }

    // ---- Phase 5: fixup + store (off the critical chain) ----
#pragma unroll
    for (int i = 0; i < LL; i++) {
        __stcs(op + i * HH, fmaf(cc[i], h0, vv[i]));
    }
}

extern "C" void kernel_launch(void* const* d_in, const int* in_sizes, int n_in,
                              void* d_out, int out_size)
{
    const float* log_coeffs = (const float*)d_in[0];   // (B, T, H)
    const float* log_values = (const float*)d_in[1];   // (B, T+1, H)
    float*       out        = (float*)d_out;           // (B, T, H)

    const int blocks = CC * NCOL;      // 64 * 128 = 8192, chunk-major
    minrnn_ab_kernel<<<blocks, 128>>>(log_coeffs, log_values, out);
}